// round 10
// baseline (speedup 1.0000x reference)
#include <cuda_runtime.h>
#include <math.h>
#include <stdint.h>

// Problem constants
#define BB     8
#define NSEQ   512
#define DIMD   512
#define DEPTH  6
#define HEADS  8
#define DH     64
#define INNER  512          // HEADS*DH
#define ROWS   4096         // BB*NSEQ
#define EPSL   1e-5f
#define ASCALE 0.125f       // DH^-0.5

// ---------------------------------------------------------------------------
// Scratch: 32 MB of __device__ globals. w/qkv buffer lives in d_out.
// x and z ping-pong as the residual-stream buffer across layers.
// ---------------------------------------------------------------------------
__device__ float g_x_r[ROWS * DIMD];
__device__ float g_x_i[ROWS * DIMD];
__device__ float g_z_r[ROWS * DIMD];
__device__ float g_z_i[ROWS * DIMD];

// ---------------------------------------------------------------------------
// Common mma/split helpers (verified R5-R9)
// ---------------------------------------------------------------------------
__device__ __forceinline__ void mma16(float* c, const uint32_t* a, const uint32_t* b) {
    asm volatile(
        "mma.sync.aligned.m16n8k16.row.col.f32.bf16.bf16.f32 "
        "{%0,%1,%2,%3}, {%4,%5,%6,%7}, {%8,%9}, {%0,%1,%2,%3};\n"
        : "+f"(c[0]), "+f"(c[1]), "+f"(c[2]), "+f"(c[3])
        : "r"(a[0]), "r"(a[1]), "r"(a[2]), "r"(a[3]), "r"(b[0]), "r"(b[1]));
}
__device__ __forceinline__ uint32_t pkbf(float lo_val, float hi_val) {
    uint32_t r;
    asm("cvt.rn.bf16x2.f32 %0, %1, %2;" : "=r"(r) : "f"(hi_val), "f"(lo_val));
    return r;
}
__device__ __forceinline__ uint32_t hi2(float a, float b) {
    uint32_t r;
    asm("prmt.b32 %0, %1, %2, 0x7632;" : "=r"(r)
        : "r"(__float_as_uint(a)), "r"(__float_as_uint(b)));
    return r;
}
__device__ __forceinline__ float lof(float a) {
    return a - __uint_as_float(__float_as_uint(a) & 0xffff0000u);
}
__device__ __forceinline__ void st_split(uint16_t* hiP, uint16_t* loP, int e, float4 v) {
    *(uint2*)&hiP[e] = make_uint2(hi2(v.x, v.y), hi2(v.z, v.w));
    *(uint2*)&loP[e] = make_uint2(pkbf(lof(v.x), lof(v.y)), pkbf(lof(v.z), lof(v.w)));
}
__device__ __forceinline__ void ldsm4(uint32_t* d, const uint16_t* p) {
    uint32_t a = (uint32_t)__cvta_generic_to_shared(p);
    asm volatile("ldmatrix.sync.aligned.m8n8.x4.shared.b16 {%0,%1,%2,%3}, [%4];"
        : "=r"(d[0]), "=r"(d[1]), "=r"(d[2]), "=r"(d[3]) : "r"(a));
}
__device__ __forceinline__ void ldsm4t(uint32_t* d, const uint16_t* p) {
    uint32_t a = (uint32_t)__cvta_generic_to_shared(p);
    asm volatile("ldmatrix.sync.aligned.m8n8.x4.trans.shared.b16 {%0,%1,%2,%3}, [%4];"
        : "=r"(d[0]), "=r"(d[1]), "=r"(d[2]), "=r"(d[3]) : "r"(a));
}

// ---------------------------------------------------------------------------
// bf16x3 split-precision complex NT GEMM, LD32 fragment loads (R8 body),
// optional fused ComplexLayerNorm on A (LN=1) and fused epilogues:
//   EPI 0: plain store
//   EPI 1: C += result + bias (residual)       [A = ao, no LN]
//   EPI 2: C = CReLU(z2 + ps*result - ps*pl)   [A = x, LN=1; z2 recomputed]
// CTA tile 128x128, BK=16, 256 threads, warp tile 32x64, double-buffered.
// ---------------------------------------------------------------------------
#define PADK 24
#define APLN (128 * PADK)
#define STG  (8 * APLN)
#define CG_SMEM_PLANES (2 * STG * 2)                 // 98304 bytes
#define CG_SMEM_TOT (CG_SMEM_PLANES + 2560 * 4)      // + stats/gamma/beta = 108544

#define LD32(P, r, k) (*(const uint32_t*)&(P)[(r) * PADK + (k)])

template <int EPI, int LN>
__global__ __launch_bounds__(256) void cgemm_bf16x3(
    const float* __restrict__ Ar, const float* __restrict__ Ai, int lda,
    const float* __restrict__ Br, const float* __restrict__ Bi, int ldb,
    float* __restrict__ Cr, float* __restrict__ Ci, int ldc, int K,
    const float* __restrict__ biasr, const float* __restrict__ biasi,
    const float* __restrict__ stepp, const float* __restrict__ lamp, int l,
    const float* __restrict__ lngr, const float* __restrict__ lnbr,
    const float* __restrict__ lngi, const float* __restrict__ lnbi)
{
    extern __shared__ char smraw[];
    uint16_t* smem16 = (uint16_t*)smraw;
    float* fx = (float*)(smraw + CG_SMEM_PLANES);
    float* s_mr = fx;          float* s_rr = fx + 128;
    float* s_mi = fx + 256;    float* s_ri = fx + 384;
    float* sgr  = fx + 512;    float* sbr  = fx + 1024;
    float* sgi  = fx + 1536;   float* sbi  = fx + 2048;

    int tid = threadIdx.x;
    int lane = tid & 31, w = tid >> 5;
    int wm = (w & 3) * 32, wn = (w >> 2) * 64;
    int gid = lane >> 2, tig = lane & 3;
    int row0 = blockIdx.y * 128, col0 = blockIdx.x * 128;

    if (LN) {
        // gamma/beta to smem
        for (int i = tid; i < 512; i += 256) {
            sgr[i] = lngr[i]; sbr[i] = lnbr[i];
            sgi[i] = lngi[i]; sbi[i] = lnbi[i];
        }
        // per-row mean/rstd: threads 0-127 real, 128-255 imag
        int r = tid & 127;
        const float* p = ((tid < 128) ? Ar : Ai) + (size_t)(row0 + r) * lda;
        float s = 0.0f, ss = 0.0f;
        #pragma unroll 8
        for (int k2 = 0; k2 < 512; k2 += 4) {
            float4 v = *(const float4*)&p[k2];
            s  += v.x + v.y + v.z + v.w;
            ss += v.x * v.x + v.y * v.y + v.z * v.z + v.w * v.w;
        }
        float mean = s * (1.0f / 512.0f);
        float var  = fmaxf(ss * (1.0f / 512.0f) - mean * mean, 0.0f);
        float rstd = rsqrtf(var + EPSL);
        if (tid < 128) { s_mr[r] = mean; s_rr[r] = rstd; }
        else           { s_mi[r] = mean; s_ri[r] = rstd; }
        __syncthreads();
    }

    float cr[2][8][4] = {}, ci[2][8][4] = {};
    float4 pa_r[2], pa_i[2], pb_r[2], pb_i[2];

    #define FETCH(k0)                                                          \
        {                                                                      \
            _Pragma("unroll")                                                  \
            for (int i = 0; i < 2; i++) {                                      \
                int idx = tid + i * 256;                                       \
                int m = idx >> 2, kq = idx & 3;                                \
                pa_r[i] = *(const float4*)&Ar[(size_t)(row0 + m) * lda + (k0) + kq * 4]; \
                pa_i[i] = *(const float4*)&Ai[(size_t)(row0 + m) * lda + (k0) + kq * 4]; \
                if (LN) {                                                      \
                    int kb = (k0) + kq * 4;                                    \
                    float mr = s_mr[m], rr = s_rr[m];                          \
                    float mi = s_mi[m], ri = s_ri[m];                          \
                    pa_r[i].x = (pa_r[i].x - mr) * rr * sgr[kb + 0] + sbr[kb + 0]; \
                    pa_r[i].y = (pa_r[i].y - mr) * rr * sgr[kb + 1] + sbr[kb + 1]; \
                    pa_r[i].z = (pa_r[i].z - mr) * rr * sgr[kb + 2] + sbr[kb + 2]; \
                    pa_r[i].w = (pa_r[i].w - mr) * rr * sgr[kb + 3] + sbr[kb + 3]; \
                    pa_i[i].x = (pa_i[i].x - mi) * ri * sgi[kb + 0] + sbi[kb + 0]; \
                    pa_i[i].y = (pa_i[i].y - mi) * ri * sgi[kb + 1] + sbi[kb + 1]; \
                    pa_i[i].z = (pa_i[i].z - mi) * ri * sgi[kb + 2] + sbi[kb + 2]; \
                    pa_i[i].w = (pa_i[i].w - mi) * ri * sgi[kb + 3] + sbi[kb + 3]; \
                }                                                              \
                pb_r[i] = *(const float4*)&Br[(size_t)(col0 + m) * ldb + (k0) + kq * 4]; \
                pb_i[i] = *(const float4*)&Bi[(size_t)(col0 + m) * ldb + (k0) + kq * 4]; \
            }                                                                  \
        }

    #define STORE_SM(base)                                                     \
        {                                                                      \
            _Pragma("unroll")                                                  \
            for (int i = 0; i < 2; i++) {                                      \
                int idx = tid + i * 256;                                       \
                int m = idx >> 2, kq = idx & 3;                                \
                int e = m * PADK + kq * 4;                                     \
                st_split((base),            (base) + APLN,     e, pa_r[i]);    \
                st_split((base) + 2 * APLN, (base) + 3 * APLN, e, pa_i[i]);    \
                st_split((base) + 4 * APLN, (base) + 5 * APLN, e, pb_r[i]);    \
                st_split((base) + 6 * APLN, (base) + 7 * APLN, e, pb_i[i]);    \
            }                                                                  \
        }

    FETCH(0);
    STORE_SM(smem16);
    __syncthreads();

    int nstage = K >> 4;
    for (int s = 0; s < nstage; s++) {
        uint16_t* cur = smem16 + (s & 1) * STG;
        uint16_t* nxt = smem16 + ((s + 1) & 1) * STG;
        if (s + 1 < nstage) FETCH((s + 1) * 16);

        const uint16_t* ARH = cur;
        const uint16_t* ARL = cur + APLN;
        const uint16_t* AIH = cur + 2 * APLN;
        const uint16_t* AIL = cur + 3 * APLN;
        const uint16_t* BRH = cur + 4 * APLN;
        const uint16_t* BRL = cur + 5 * APLN;
        const uint16_t* BIH = cur + 6 * APLN;
        const uint16_t* BIL = cur + 7 * APLN;

        int kk = tig * 2;
        uint32_t aRH[2][4], aRL[2][4], aIH[2][4], aIL[2][4];
        #pragma unroll
        for (int mt = 0; mt < 2; mt++) {
            int r = wm + mt * 16 + gid;
            aRH[mt][0] = LD32(ARH, r, kk);     aRH[mt][1] = LD32(ARH, r + 8, kk);
            aRH[mt][2] = LD32(ARH, r, kk + 8); aRH[mt][3] = LD32(ARH, r + 8, kk + 8);
            aRL[mt][0] = LD32(ARL, r, kk);     aRL[mt][1] = LD32(ARL, r + 8, kk);
            aRL[mt][2] = LD32(ARL, r, kk + 8); aRL[mt][3] = LD32(ARL, r + 8, kk + 8);
            aIH[mt][0] = LD32(AIH, r, kk);     aIH[mt][1] = LD32(AIH, r + 8, kk);
            aIH[mt][2] = LD32(AIH, r, kk + 8); aIH[mt][3] = LD32(AIH, r + 8, kk + 8);
            aIL[mt][0] = LD32(AIL, r, kk);     aIL[mt][1] = LD32(AIL, r + 8, kk);
            aIL[mt][2] = LD32(AIL, r, kk + 8); aIL[mt][3] = LD32(AIL, r + 8, kk + 8);
        }
        #pragma unroll
        for (int nt = 0; nt < 8; nt++) {
            int c = wn + nt * 8 + gid;
            uint32_t bRH[2] = { LD32(BRH, c, kk), LD32(BRH, c, kk + 8) };
            uint32_t bRL[2] = { LD32(BRL, c, kk), LD32(BRL, c, kk + 8) };
            uint32_t bIH[2] = { LD32(BIH, c, kk), LD32(BIH, c, kk + 8) };
            uint32_t bIL[2] = { LD32(BIL, c, kk), LD32(BIL, c, kk + 8) };
            uint32_t nIH[2] = { bIH[0] ^ 0x80008000u, bIH[1] ^ 0x80008000u };
            uint32_t nIL[2] = { bIL[0] ^ 0x80008000u, bIL[1] ^ 0x80008000u };
            #pragma unroll
            for (int mt = 0; mt < 2; mt++) {
                mma16(cr[mt][nt], aRH[mt], bRH);
                mma16(cr[mt][nt], aRH[mt], bRL);
                mma16(cr[mt][nt], aRL[mt], bRH);
                mma16(cr[mt][nt], aIH[mt], nIH);
                mma16(cr[mt][nt], aIH[mt], nIL);
                mma16(cr[mt][nt], aIL[mt], nIH);
                mma16(ci[mt][nt], aRH[mt], bIH);
                mma16(ci[mt][nt], aRH[mt], bIL);
                mma16(ci[mt][nt], aRL[mt], bIH);
                mma16(ci[mt][nt], aIH[mt], bRH);
                mma16(ci[mt][nt], aIH[mt], bRL);
                mma16(ci[mt][nt], aIL[mt], bRH);
            }
        }

        if (s + 1 < nstage) STORE_SM(nxt);
        __syncthreads();
    }
    #undef FETCH
    #undef STORE_SM

    float ps = 0.0f, pl = 0.0f;
    if (EPI == 2) {
        ps = log1pf(expf(stepp[l]));
        pl = log1pf(expf(lamp[l]));
    }

    #pragma unroll
    for (int mt = 0; mt < 2; mt++)
        #pragma unroll
        for (int nt = 0; nt < 8; nt++) {
            int m0 = row0 + wm + mt * 16 + gid;
            int n0 = col0 + wn + nt * 8 + tig * 2;
            #pragma unroll
            for (int half = 0; half < 2; half++) {
                int m = m0 + half * 8;
                float vr0 = cr[mt][nt][half * 2 + 0];
                float vr1 = cr[mt][nt][half * 2 + 1];
                float vi0 = ci[mt][nt][half * 2 + 0];
                float vi1 = ci[mt][nt][half * 2 + 1];
                size_t idx = (size_t)m * ldc + n0;
                if (EPI == 0) {
                    Cr[idx]     = vr0;  Cr[idx + 1] = vr1;
                    Ci[idx]     = vi0;  Ci[idx + 1] = vi1;
                } else if (EPI == 1) {
                    Cr[idx]     += vr0 + biasr[n0];
                    Cr[idx + 1] += vr1 + biasr[n0 + 1];
                    Ci[idx]     += vi0 + biasi[n0];
                    Ci[idx + 1] += vi1 + biasi[n0 + 1];
                } else {
                    // recompute z2[m][n] from raw x + row stats (LN=1 here)
                    int rl = m - row0;
                    float mr = s_mr[rl], rr = s_rr[rl];
                    float mi = s_mi[rl], ri = s_ri[rl];
                    size_t za = (size_t)m * lda + n0;
                    float zr0 = (Ar[za]     - mr) * rr * sgr[n0]     + sbr[n0];
                    float zr1 = (Ar[za + 1] - mr) * rr * sgr[n0 + 1] + sbr[n0 + 1];
                    float zi0 = (Ai[za]     - mi) * ri * sgi[n0]     + sbi[n0];
                    float zi1 = (Ai[za + 1] - mi) * ri * sgi[n0 + 1] + sbi[n0 + 1];
                    Cr[idx]     = fmaxf(zr0 + ps * vr0 - ps * pl, 0.0f);
                    Cr[idx + 1] = fmaxf(zr1 + ps * vr1 - ps * pl, 0.0f);
                    Ci[idx]     = fmaxf(zi0 + ps * vi0, 0.0f);
                    Ci[idx + 1] = fmaxf(zi1 + ps * vi1, 0.0f);
                }
            }
        }
}

// ---------------------------------------------------------------------------
// Tensor-core flash attention (bf16x3), 64 q-rows / 4 warps per CTA,
// 2 CTAs per SM (R9 version, measured faster than 128-row R8).
// ---------------------------------------------------------------------------
#define FSTR 72
#define QPL (64 * FSTR)
#define KPL (64 * FSTR)
#define FLASH_SMEM ((4 * QPL + 4 * KPL) * 2)   // 73728 bytes

__global__ __launch_bounds__(128, 2) void flash_mma_kernel(
    const float* __restrict__ Wr, const float* __restrict__ Wi,
    float* __restrict__ Or, float* __restrict__ Oi)
{
    extern __shared__ uint16_t fsm[];
    uint16_t* QRH = fsm;
    uint16_t* QRL = QRH + QPL;
    uint16_t* QIH = QRL + QPL;
    uint16_t* QIL = QIH + QPL;
    uint16_t* KRH = QIL + QPL;
    uint16_t* KRL = KRH + KPL;
    uint16_t* KIH = KRL + KPL;
    uint16_t* KIL = KIH + KPL;

    int tid = threadIdx.x;
    int lane = tid & 31, w = tid >> 5;   // w in 0..3
    int q0 = blockIdx.x * 64;
    int bh = blockIdx.y;
    int b = bh >> 3, h = bh & 7;

    const float* baseR = Wr + (size_t)b * NSEQ * INNER + h * DH;
    const float* baseI = Wi + (size_t)b * NSEQ * INNER + h * DH;

    #pragma unroll
    for (int i = 0; i < 8; i++) {
        int linear = tid + i * 128;
        int row = linear >> 4, c4 = linear & 15;
        float4 v = *(const float4*)&baseR[(size_t)(q0 + row) * INNER + c4 * 4];
        st_split(QRH, QRL, row * FSTR + c4 * 4, v);
        v = *(const float4*)&baseI[(size_t)(q0 + row) * INNER + c4 * 4];
        st_split(QIH, QIL, row * FSTR + c4 * 4, v);
    }

    int a_off = (16 * w + (lane & 7) + ((lane >> 3) & 1) * 8) * FSTR
              + ((lane >> 4) & 1) * 8;
    int bd_off = ((lane & 7) + ((lane >> 4) & 1) * 8) * FSTR
               + ((lane >> 3) & 1) * 8;
    int bv_off = ((lane & 7) + ((lane >> 3) & 1) * 8) * FSTR
               + ((lane >> 4) & 1) * 8;

    float o_r[8][4] = {}, o_i[8][4] = {};
    float mrow[2] = { -1e30f, -1e30f };
    float lrow[2] = { 0.0f, 0.0f };

    for (int kt = 0; kt < 8; kt++) {
        __syncthreads();
        #pragma unroll
        for (int i = 0; i < 8; i++) {
            int linear = tid + i * 128;
            int key = linear >> 4, c4 = linear & 15;
            int e = key * FSTR + c4 * 4;
            float4 v = *(const float4*)&baseR[(size_t)(kt * 64 + key) * INNER + c4 * 4];
            st_split(KRH, KRL, e, v);
            v = *(const float4*)&baseI[(size_t)(kt * 64 + key) * INNER + c4 * 4];
            st_split(KIH, KIL, e, v);
        }
        __syncthreads();

        // ---- dots ----
        float dr[8][4] = {}, di[8][4] = {};
        #pragma unroll 1
        for (int ks = 0; ks < 4; ks++) {
            int ao = a_off + ks * 16;
            uint32_t aRH[4], aRL[4], aIH[4], aIL[4];
            ldsm4(aRH, QRH + ao); ldsm4(aRL, QRL + ao);
            ldsm4(aIH, QIH + ao); ldsm4(aIL, QIL + ao);
            #pragma unroll
            for (int nfp = 0; nfp < 4; nfp++) {
                int bo = bd_off + nfp * 16 * FSTR + ks * 16;
                uint32_t BRH[4], BRL[4], BIH[4], BIL[4];
                ldsm4(BRH, KRH + bo); ldsm4(BRL, KRL + bo);
                ldsm4(BIH, KIH + bo); ldsm4(BIL, KIL + bo);
                #pragma unroll
                for (int half = 0; half < 2; half++) {
                    int nf = 2 * nfp + half;
                    uint32_t bRH[2] = { BRH[2*half], BRH[2*half+1] };
                    uint32_t bRL[2] = { BRL[2*half], BRL[2*half+1] };
                    uint32_t bIH[2] = { BIH[2*half], BIH[2*half+1] };
                    uint32_t bIL[2] = { BIL[2*half], BIL[2*half+1] };
                    uint32_t nIH[2] = { bIH[0] ^ 0x80008000u, bIH[1] ^ 0x80008000u };
                    uint32_t nIL[2] = { bIL[0] ^ 0x80008000u, bIL[1] ^ 0x80008000u };
                    mma16(dr[nf], aRH, bRH); mma16(dr[nf], aRH, bRL); mma16(dr[nf], aRL, bRH);
                    mma16(dr[nf], aIH, bIH); mma16(dr[nf], aIH, bIL); mma16(dr[nf], aIL, bIH);
                    mma16(di[nf], aIH, bRH); mma16(di[nf], aIH, bRL); mma16(di[nf], aIL, bRH);
                    mma16(di[nf], aRH, nIH); mma16(di[nf], aRH, nIL); mma16(di[nf], aRL, nIH);
                }
            }
        }

        // ---- online softmax ----
        float m2max[2] = { -1.0f, -1.0f };
        #pragma unroll
        for (int nf = 0; nf < 8; nf++)
            #pragma unroll
            for (int e = 0; e < 4; e++) {
                float m2 = dr[nf][e] * dr[nf][e] + di[nf][e] * di[nf][e];
                m2max[e >> 1] = fmaxf(m2max[e >> 1], m2);
            }
        float mnew[2];
        #pragma unroll
        for (int half = 0; half < 2; half++) {
            float v = m2max[half];
            v = fmaxf(v, __shfl_xor_sync(0xffffffffu, v, 1));
            v = fmaxf(v, __shfl_xor_sync(0xffffffffu, v, 2));
            mnew[half] = fmaxf(mrow[half], ASCALE * sqrtf(fmaxf(v, 0.0f)));
        }
        float sc0 = __expf(mrow[0] - mnew[0]);
        float sc1 = __expf(mrow[1] - mnew[1]);
        lrow[0] *= sc0; lrow[1] *= sc1;
        mrow[0] = mnew[0]; mrow[1] = mnew[1];
        #pragma unroll
        for (int nf = 0; nf < 8; nf++) {
            o_r[nf][0] *= sc0; o_r[nf][1] *= sc0;
            o_r[nf][2] *= sc1; o_r[nf][3] *= sc1;
            o_i[nf][0] *= sc0; o_i[nf][1] *= sc0;
            o_i[nf][2] *= sc1; o_i[nf][3] *= sc1;
        }
        float rsum[2] = { 0.0f, 0.0f };
        #pragma unroll
        for (int nf = 0; nf < 8; nf++)
            #pragma unroll
            for (int e = 0; e < 4; e++) {
                float m2 = dr[nf][e] * dr[nf][e] + di[nf][e] * di[nf][e];
                if (m2 > 0.0f) {
                    float rs = rsqrtf(m2);
                    float s = m2 * rs;
                    float p = __expf(ASCALE * s - mrow[e >> 1]);
                    rsum[e >> 1] += p;
                    float f = p * rs;
                    dr[nf][e] *= f;
                    di[nf][e] *= f;
                } else {
                    float p = __expf(-mrow[e >> 1]);
                    rsum[e >> 1] += p;
                    dr[nf][e] = p;
                    di[nf][e] = 0.0f;
                }
            }
        #pragma unroll
        for (int half = 0; half < 2; half++) {
            float v = rsum[half];
            v += __shfl_xor_sync(0xffffffffu, v, 1);
            v += __shfl_xor_sync(0xffffffffu, v, 2);
            lrow[half] += v;
        }

        // ---- AV ----
        #pragma unroll
        for (int t = 0; t < 4; t++) {
            uint32_t PrH[4] = { hi2(dr[2*t][0], dr[2*t][1]),   hi2(dr[2*t][2], dr[2*t][3]),
                                hi2(dr[2*t+1][0], dr[2*t+1][1]), hi2(dr[2*t+1][2], dr[2*t+1][3]) };
            uint32_t PrL[4] = { pkbf(lof(dr[2*t][0]), lof(dr[2*t][1])),
                                pkbf(lof(dr[2*t][2]), lof(dr[2*t][3])),
                                pkbf(lof(dr[2*t+1][0]), lof(dr[2*t+1][1])),
                                pkbf(lof(dr[2*t+1][2]), lof(dr[2*t+1][3])) };
            uint32_t PiH[4] = { hi2(di[2*t][0], di[2*t][1]),   hi2(di[2*t][2], di[2*t][3]),
                                hi2(di[2*t+1][0], di[2*t+1][1]), hi2(di[2*t+1][2], di[2*t+1][3]) };
            uint32_t PiL[4] = { pkbf(lof(di[2*t][0]), lof(di[2*t][1])),
                                pkbf(lof(di[2*t][2]), lof(di[2*t][3])),
                                pkbf(lof(di[2*t+1][0]), lof(di[2*t+1][1])),
                                pkbf(lof(di[2*t+1][2]), lof(di[2*t+1][3])) };
            #pragma unroll
            for (int nfp = 0; nfp < 4; nfp++) {
                int bo = bv_off + t * 16 * FSTR + nfp * 16;
                uint32_t BRH[4], BRL[4], BIH[4], BIL[4];
                ldsm4t(BRH, KRH + bo); ldsm4t(BRL, KRL + bo);
                ldsm4t(BIH, KIH + bo); ldsm4t(BIL, KIL + bo);
                #pragma unroll
                for (int half = 0; half < 2; half++) {
                    int nf = 2 * nfp + half;
                    uint32_t bRH[2] = { BRH[2*half], BRH[2*half+1] };
                    uint32_t bRL[2] = { BRL[2*half], BRL[2*half+1] };
                    uint32_t bIH[2] = { BIH[2*half], BIH[2*half+1] };
                    uint32_t bIL[2] = { BIL[2*half], BIL[2*half+1] };
                    uint32_t nIH[2] = { bIH[0] ^ 0x80008000u, bIH[1] ^ 0x80008000u };
                    uint32_t nIL[2] = { bIL[0] ^ 0x80008000u, bIL[1] ^ 0x80008000u };
                    mma16(o_r[nf], PrH, bRH); mma16(o_r[nf], PrH, bRL); mma16(o_r[nf], PrL, bRH);
                    mma16(o_r[nf], PiH, nIH); mma16(o_r[nf], PiH, nIL); mma16(o_r[nf], PiL, nIH);
                    mma16(o_i[nf], PrH, bIH); mma16(o_i[nf], PrH, bIL); mma16(o_i[nf], PrL, bIH);
                    mma16(o_i[nf], PiH, bRH); mma16(o_i[nf], PiH, bRL); mma16(o_i[nf], PiL, bRH);
                }
            }
        }
    }

    // ---- normalize + write O ----
    int gid = lane >> 2, tig = lane & 3;
    float inv0 = 1.0f / lrow[0];
    float inv1 = 1.0f / lrow[1];
    size_t row0g = (size_t)(b * NSEQ + q0 + 16 * w + gid);
    #pragma unroll
    for (int nf = 0; nf < 8; nf++) {
        int col = h * DH + nf * 8 + tig * 2;
        *(float2*)&Or[row0g * INNER + col] =
            make_float2(o_r[nf][0] * inv0, o_r[nf][1] * inv0);
        *(float2*)&Or[(row0g + 8) * INNER + col] =
            make_float2(o_r[nf][2] * inv1, o_r[nf][3] * inv1);
        *(float2*)&Oi[row0g * INNER + col] =
            make_float2(o_i[nf][0] * inv0, o_i[nf][1] * inv0);
        *(float2*)&Oi[(row0g + 8) * INNER + col] =
            make_float2(o_i[nf][2] * inv1, o_i[nf][3] * inv1);
    }
}

__global__ __launch_bounds__(256) void init_kernel(
    const float* __restrict__ xr, const float* __restrict__ xi)
{
    int i = blockIdx.x * 256 + threadIdx.x;
    g_x_r[i] = xr[i];
    g_x_i[i] = xi[i];
}

__global__ __launch_bounds__(256) void output_kernel(
    const float* __restrict__ xr, const float* __restrict__ xi,
    float* __restrict__ out)
{
    int i = blockIdx.x * 256 + threadIdx.x;
    out[i] = xr[i];
    out[i + ROWS * DIMD] = xi[i];
}

// ---------------------------------------------------------------------------
// Launch
// ---------------------------------------------------------------------------
extern "C" void kernel_launch(void* const* d_in, const int* in_sizes, int n_in,
                              void* d_out, int out_size)
{
    const float* x_r   = (const float*)d_in[0];
    const float* x_i   = (const float*)d_in[1];
    const float* ln1gr = (const float*)d_in[2];
    const float* ln1gi = (const float*)d_in[3];
    const float* ln2gr = (const float*)d_in[4];
    const float* ln2gi = (const float*)d_in[5];
    const float* ln1br = (const float*)d_in[6];
    const float* ln1bi = (const float*)d_in[7];
    const float* ln2br = (const float*)d_in[8];
    const float* ln2bi = (const float*)d_in[9];
    const float* qkvwr = (const float*)d_in[10];
    const float* qkvwi = (const float*)d_in[11];
    const float* outwr = (const float*)d_in[12];
    const float* outwi = (const float*)d_in[13];
    const float* outbr = (const float*)d_in[14];
    const float* outbi = (const float*)d_in[15];
    const float* ffwr  = (const float*)d_in[16];
    const float* ffwi  = (const float*)d_in[17];
    const float* stepv = (const float*)d_in[18];
    const float* lambv = (const float*)d_in[19];

    const int EW = ROWS * DIMD;
    const dim3 gemm_grid(DIMD / 128, ROWS / 128);   // (4, 32) = 128 blocks

    float* wr = (float*)d_out;
    float* wi = wr + (size_t)ROWS * INNER;

    float *xr, *xi, *zr, *zi;
    cudaGetSymbolAddress((void**)&xr, g_x_r);
    cudaGetSymbolAddress((void**)&xi, g_x_i);
    cudaGetSymbolAddress((void**)&zr, g_z_r);
    cudaGetSymbolAddress((void**)&zi, g_z_i);

    cudaFuncSetAttribute(flash_mma_kernel,
                         cudaFuncAttributeMaxDynamicSharedMemorySize, FLASH_SMEM);
    cudaFuncSetAttribute((const void*)cgemm_bf16x3<0, 1>,
                         cudaFuncAttributeMaxDynamicSharedMemorySize, CG_SMEM_TOT);
    cudaFuncSetAttribute((const void*)cgemm_bf16x3<1, 0>,
                         cudaFuncAttributeMaxDynamicSharedMemorySize, CG_SMEM_TOT);
    cudaFuncSetAttribute((const void*)cgemm_bf16x3<2, 1>,
                         cudaFuncAttributeMaxDynamicSharedMemorySize, CG_SMEM_TOT);

    init_kernel<<<EW / 256, 256>>>(x_r, x_i);

    // residual-stream ping-pong buffers
    float *Xr = xr, *Xi = xi, *Zr = zr, *Zi = zi;

    for (int l = 0; l < DEPTH; l++) {
        const float* qr  = qkvwr + (size_t)l * INNER * DIMD;
        const float* qi  = qkvwi + (size_t)l * INNER * DIMD;
        const float* owr = outwr + (size_t)l * DIMD * INNER;
        const float* owi = outwi + (size_t)l * DIMD * INNER;
        const float* fwr = ffwr + (size_t)l * DIMD * DIMD;
        const float* fwi = ffwi + (size_t)l * DIMD * DIMD;

        // w = LN1(x) @ Wqkv^T   (LN fused into A fetch)
        cgemm_bf16x3<0, 1><<<gemm_grid, 256, CG_SMEM_TOT>>>(
            Xr, Xi, DIMD, qr, qi, DIMD, wr, wi, INNER, DIMD,
            nullptr, nullptr, nullptr, nullptr, 0,
            ln1gr + l * DIMD, ln1br + l * DIMD, ln1gi + l * DIMD, ln1bi + l * DIMD);
        // ao = attention(w) -> Z buffer
        flash_mma_kernel<<<dim3(NSEQ / 64, BB * HEADS), 128, FLASH_SMEM>>>(wr, wi, Zr, Zi);
        // x += ao @ Wout^T + bias   (in-place on X)
        cgemm_bf16x3<1, 0><<<gemm_grid, 256, CG_SMEM_TOT>>>(
            Zr, Zi, INNER, owr, owi, INNER, Xr, Xi, DIMD, INNER,
            outbr + l * DIMD, outbi + l * DIMD, nullptr, nullptr, 0,
            nullptr, nullptr, nullptr, nullptr);
        // z_next = CReLU(LN2(x) + ps*(LN2(x) @ Wff^T) - ps*pl)  -> Z buffer
        cgemm_bf16x3<2, 1><<<gemm_grid, 256, CG_SMEM_TOT>>>(
            Xr, Xi, DIMD, fwr, fwi, DIMD, Zr, Zi, DIMD, DIMD,
            nullptr, nullptr, stepv, lambv, l,
            ln2gr + l * DIMD, ln2br + l * DIMD, ln2gi + l * DIMD, ln2bi + l * DIMD);

        // ping-pong
        float* t;
        t = Xr; Xr = Zr; Zr = t;
        t = Xi; Xi = Zi; Zi = t;
    }

    output_kernel<<<EW / 256, 256>>>(Xr, Xi, (float*)d_out);
}

// round 11
// speedup vs baseline: 1.0453x; 1.0453x over previous
#include <cuda_runtime.h>
#include <math.h>
#include <stdint.h>

// Problem constants
#define BB     8
#define NSEQ   512
#define DIMD   512
#define DEPTH  6
#define HEADS  8
#define DH     64
#define INNER  512          // HEADS*DH
#define ROWS   4096         // BB*NSEQ
#define EPSL   1e-5f
#define ASCALE 0.125f       // DH^-0.5

// ---------------------------------------------------------------------------
// Scratch: 32 MB of __device__ globals. w/qkv buffer lives in d_out.
// ---------------------------------------------------------------------------
__device__ float g_x_r[ROWS * DIMD];
__device__ float g_x_i[ROWS * DIMD];
__device__ float g_z_r[ROWS * DIMD];
__device__ float g_z_i[ROWS * DIMD];

// ---------------------------------------------------------------------------
// Common mma/split helpers (verified R5-R9)
// ---------------------------------------------------------------------------
__device__ __forceinline__ void mma16(float* c, const uint32_t* a, const uint32_t* b) {
    asm volatile(
        "mma.sync.aligned.m16n8k16.row.col.f32.bf16.bf16.f32 "
        "{%0,%1,%2,%3}, {%4,%5,%6,%7}, {%8,%9}, {%0,%1,%2,%3};\n"
        : "+f"(c[0]), "+f"(c[1]), "+f"(c[2]), "+f"(c[3])
        : "r"(a[0]), "r"(a[1]), "r"(a[2]), "r"(a[3]), "r"(b[0]), "r"(b[1]));
}
__device__ __forceinline__ uint32_t pkbf(float lo_val, float hi_val) {
    uint32_t r;
    asm("cvt.rn.bf16x2.f32 %0, %1, %2;" : "=r"(r) : "f"(hi_val), "f"(lo_val));
    return r;
}
__device__ __forceinline__ uint32_t hi2(float a, float b) {
    uint32_t r;
    asm("prmt.b32 %0, %1, %2, 0x7632;" : "=r"(r)
        : "r"(__float_as_uint(a)), "r"(__float_as_uint(b)));
    return r;
}
__device__ __forceinline__ float lof(float a) {
    return a - __uint_as_float(__float_as_uint(a) & 0xffff0000u);
}
__device__ __forceinline__ void st_split(uint16_t* hiP, uint16_t* loP, int e, float4 v) {
    *(uint2*)&hiP[e] = make_uint2(hi2(v.x, v.y), hi2(v.z, v.w));
    *(uint2*)&loP[e] = make_uint2(pkbf(lof(v.x), lof(v.y)), pkbf(lof(v.z), lof(v.w)));
}
__device__ __forceinline__ void ldsm4(uint32_t* d, const uint16_t* p) {
    uint32_t a = (uint32_t)__cvta_generic_to_shared(p);
    asm volatile("ldmatrix.sync.aligned.m8n8.x4.shared.b16 {%0,%1,%2,%3}, [%4];"
        : "=r"(d[0]), "=r"(d[1]), "=r"(d[2]), "=r"(d[3]) : "r"(a));
}
__device__ __forceinline__ void ldsm4t(uint32_t* d, const uint16_t* p) {
    uint32_t a = (uint32_t)__cvta_generic_to_shared(p);
    asm volatile("ldmatrix.sync.aligned.m8n8.x4.trans.shared.b16 {%0,%1,%2,%3}, [%4];"
        : "=r"(d[0]), "=r"(d[1]), "=r"(d[2]), "=r"(d[3]) : "r"(a));
}

// ---------------------------------------------------------------------------
// Block reduction helper (256 threads)
// ---------------------------------------------------------------------------
__device__ __forceinline__ float block_reduce(float v, float* sh, bool ismax) {
    #pragma unroll
    for (int o = 16; o; o >>= 1) {
        float u = __shfl_xor_sync(0xffffffffu, v, o);
        v = ismax ? fmaxf(v, u) : (v + u);
    }
    int w = threadIdx.x >> 5;
    if ((threadIdx.x & 31) == 0) sh[w] = v;
    __syncthreads();
    if (threadIdx.x < 32) {
        float u = (threadIdx.x < 8) ? sh[threadIdx.x] : (ismax ? -INFINITY : 0.0f);
        #pragma unroll
        for (int o = 4; o; o >>= 1) {
            float t2 = __shfl_xor_sync(0xffffffffu, u, o);
            u = ismax ? fmaxf(u, t2) : (u + t2);
        }
        if (threadIdx.x == 0) sh[0] = u;
    }
    __syncthreads();
    float r = sh[0];
    __syncthreads();
    return r;
}

// ---------------------------------------------------------------------------
// Complex LayerNorm. One block (256 threads) per row of 512.
// ---------------------------------------------------------------------------
__global__ __launch_bounds__(256) void cln_kernel(
    const float* __restrict__ xr, const float* __restrict__ xi,
    const float* __restrict__ gr, const float* __restrict__ br,
    const float* __restrict__ gi, const float* __restrict__ bi,
    float* __restrict__ zr, float* __restrict__ zi)
{
    __shared__ float sh[8];
    int row = blockIdx.x;
    int t = threadIdx.x;
    const float* pr = xr + (size_t)row * DIMD;
    const float* pi = xi + (size_t)row * DIMD;

    float r0 = pr[t], r1 = pr[t + 256];
    float i0 = pi[t], i1 = pi[t + 256];

    float sr  = block_reduce(r0 + r1, sh, false);
    float ssr = block_reduce(r0 * r0 + r1 * r1, sh, false);
    float si  = block_reduce(i0 + i1, sh, false);
    float ssi = block_reduce(i0 * i0 + i1 * i1, sh, false);

    float mr = sr * (1.0f / DIMD);
    float vr = fmaxf(ssr * (1.0f / DIMD) - mr * mr, 0.0f);
    float rsr = rsqrtf(vr + EPSL);
    float mi = si * (1.0f / DIMD);
    float vi = fmaxf(ssi * (1.0f / DIMD) - mi * mi, 0.0f);
    float rsi = rsqrtf(vi + EPSL);

    float* qr = zr + (size_t)row * DIMD;
    float* qi = zi + (size_t)row * DIMD;
    qr[t]       = (r0 - mr) * rsr * gr[t]       + br[t];
    qr[t + 256] = (r1 - mr) * rsr * gr[t + 256] + br[t + 256];
    qi[t]       = (i0 - mi) * rsi * gi[t]       + bi[t];
    qi[t + 256] = (i1 - mi) * rsi * gi[t + 256] + bi[t + 256];
}

// ---------------------------------------------------------------------------
// bf16x3 split-precision complex NT GEMM — exact R8 body (best measured).
// CTA tile 128x128, BK=16, 256 threads, warp tile 32x64, double-buffered,
// LD32 fragment loads. Epilogues: 0 plain / 1 residual+bias / 2 ISTA+CReLU.
// ---------------------------------------------------------------------------
#define PADK 24
#define APLN (128 * PADK)
#define STG  (8 * APLN)
#define CG_SMEM (2 * STG * 2)

#define LD32(P, r, k) (*(const uint32_t*)&(P)[(r) * PADK + (k)])

template <int EPI>
__global__ __launch_bounds__(256) void cgemm_bf16x3(
    const float* __restrict__ Ar, const float* __restrict__ Ai, int lda,
    const float* __restrict__ Br, const float* __restrict__ Bi, int ldb,
    float* __restrict__ Cr, float* __restrict__ Ci, int ldc, int K,
    const float* __restrict__ biasr, const float* __restrict__ biasi,
    const float* __restrict__ stepp, const float* __restrict__ lamp, int l)
{
    extern __shared__ uint16_t smem16[];

    int tid = threadIdx.x;
    int lane = tid & 31, w = tid >> 5;
    int wm = (w & 3) * 32, wn = (w >> 2) * 64;
    int gid = lane >> 2, tig = lane & 3;
    int row0 = blockIdx.y * 128, col0 = blockIdx.x * 128;

    float cr[2][8][4] = {}, ci[2][8][4] = {};
    float4 pa_r[2], pa_i[2], pb_r[2], pb_i[2];

    #define FETCH(k0)                                                          \
        {                                                                      \
            _Pragma("unroll")                                                  \
            for (int i = 0; i < 2; i++) {                                      \
                int idx = tid + i * 256;                                       \
                int m = idx >> 2, kq = idx & 3;                                \
                pa_r[i] = *(const float4*)&Ar[(size_t)(row0 + m) * lda + (k0) + kq * 4]; \
                pa_i[i] = *(const float4*)&Ai[(size_t)(row0 + m) * lda + (k0) + kq * 4]; \
                pb_r[i] = *(const float4*)&Br[(size_t)(col0 + m) * ldb + (k0) + kq * 4]; \
                pb_i[i] = *(const float4*)&Bi[(size_t)(col0 + m) * ldb + (k0) + kq * 4]; \
            }                                                                  \
        }

    #define STORE_SM(base)                                                     \
        {                                                                      \
            _Pragma("unroll")                                                  \
            for (int i = 0; i < 2; i++) {                                      \
                int idx = tid + i * 256;                                       \
                int m = idx >> 2, kq = idx & 3;                                \
                int e = m * PADK + kq * 4;                                     \
                st_split((base),            (base) + APLN,     e, pa_r[i]);    \
                st_split((base) + 2 * APLN, (base) + 3 * APLN, e, pa_i[i]);    \
                st_split((base) + 4 * APLN, (base) + 5 * APLN, e, pb_r[i]);    \
                st_split((base) + 6 * APLN, (base) + 7 * APLN, e, pb_i[i]);    \
            }                                                                  \
        }

    FETCH(0);
    STORE_SM(smem16);
    __syncthreads();

    int nstage = K >> 4;
    for (int s = 0; s < nstage; s++) {
        uint16_t* cur = smem16 + (s & 1) * STG;
        uint16_t* nxt = smem16 + ((s + 1) & 1) * STG;
        if (s + 1 < nstage) FETCH((s + 1) * 16);

        const uint16_t* ARH = cur;
        const uint16_t* ARL = cur + APLN;
        const uint16_t* AIH = cur + 2 * APLN;
        const uint16_t* AIL = cur + 3 * APLN;
        const uint16_t* BRH = cur + 4 * APLN;
        const uint16_t* BRL = cur + 5 * APLN;
        const uint16_t* BIH = cur + 6 * APLN;
        const uint16_t* BIL = cur + 7 * APLN;

        int kk = tig * 2;
        uint32_t aRH[2][4], aRL[2][4], aIH[2][4], aIL[2][4];
        #pragma unroll
        for (int mt = 0; mt < 2; mt++) {
            int r = wm + mt * 16 + gid;
            aRH[mt][0] = LD32(ARH, r, kk);     aRH[mt][1] = LD32(ARH, r + 8, kk);
            aRH[mt][2] = LD32(ARH, r, kk + 8); aRH[mt][3] = LD32(ARH, r + 8, kk + 8);
            aRL[mt][0] = LD32(ARL, r, kk);     aRL[mt][1] = LD32(ARL, r + 8, kk);
            aRL[mt][2] = LD32(ARL, r, kk + 8); aRL[mt][3] = LD32(ARL, r + 8, kk + 8);
            aIH[mt][0] = LD32(AIH, r, kk);     aIH[mt][1] = LD32(AIH, r + 8, kk);
            aIH[mt][2] = LD32(AIH, r, kk + 8); aIH[mt][3] = LD32(AIH, r + 8, kk + 8);
            aIL[mt][0] = LD32(AIL, r, kk);     aIL[mt][1] = LD32(AIL, r + 8, kk);
            aIL[mt][2] = LD32(AIL, r, kk + 8); aIL[mt][3] = LD32(AIL, r + 8, kk + 8);
        }
        #pragma unroll
        for (int nt = 0; nt < 8; nt++) {
            int c = wn + nt * 8 + gid;
            uint32_t bRH[2] = { LD32(BRH, c, kk), LD32(BRH, c, kk + 8) };
            uint32_t bRL[2] = { LD32(BRL, c, kk), LD32(BRL, c, kk + 8) };
            uint32_t bIH[2] = { LD32(BIH, c, kk), LD32(BIH, c, kk + 8) };
            uint32_t bIL[2] = { LD32(BIL, c, kk), LD32(BIL, c, kk + 8) };
            uint32_t nIH[2] = { bIH[0] ^ 0x80008000u, bIH[1] ^ 0x80008000u };
            uint32_t nIL[2] = { bIL[0] ^ 0x80008000u, bIL[1] ^ 0x80008000u };
            #pragma unroll
            for (int mt = 0; mt < 2; mt++) {
                mma16(cr[mt][nt], aRH[mt], bRH);
                mma16(cr[mt][nt], aRH[mt], bRL);
                mma16(cr[mt][nt], aRL[mt], bRH);
                mma16(cr[mt][nt], aIH[mt], nIH);
                mma16(cr[mt][nt], aIH[mt], nIL);
                mma16(cr[mt][nt], aIL[mt], nIH);
                mma16(ci[mt][nt], aRH[mt], bIH);
                mma16(ci[mt][nt], aRH[mt], bIL);
                mma16(ci[mt][nt], aRL[mt], bIH);
                mma16(ci[mt][nt], aIH[mt], bRH);
                mma16(ci[mt][nt], aIH[mt], bRL);
                mma16(ci[mt][nt], aIL[mt], bRH);
            }
        }

        if (s + 1 < nstage) STORE_SM(nxt);
        __syncthreads();
    }
    #undef FETCH
    #undef STORE_SM

    float ps = 0.0f, pl = 0.0f;
    if (EPI == 2) {
        ps = log1pf(expf(stepp[l]));
        pl = log1pf(expf(lamp[l]));
    }

    #pragma unroll
    for (int mt = 0; mt < 2; mt++)
        #pragma unroll
        for (int nt = 0; nt < 8; nt++) {
            int m0 = row0 + wm + mt * 16 + gid;
            int n0 = col0 + wn + nt * 8 + tig * 2;
            #pragma unroll
            for (int half = 0; half < 2; half++) {
                int m = m0 + half * 8;
                float vr0 = cr[mt][nt][half * 2 + 0];
                float vr1 = cr[mt][nt][half * 2 + 1];
                float vi0 = ci[mt][nt][half * 2 + 0];
                float vi1 = ci[mt][nt][half * 2 + 1];
                size_t idx = (size_t)m * ldc + n0;
                if (EPI == 0) {
                    Cr[idx]     = vr0;  Cr[idx + 1] = vr1;
                    Ci[idx]     = vi0;  Ci[idx + 1] = vi1;
                } else if (EPI == 1) {
                    Cr[idx]     += vr0 + biasr[n0];
                    Cr[idx + 1] += vr1 + biasr[n0 + 1];
                    Ci[idx]     += vi0 + biasi[n0];
                    Ci[idx + 1] += vi1 + biasi[n0 + 1];
                } else {
                    size_t za = (size_t)m * lda + n0;
                    Cr[idx]     = fmaxf(Ar[za]     + ps * vr0 - ps * pl, 0.0f);
                    Cr[idx + 1] = fmaxf(Ar[za + 1] + ps * vr1 - ps * pl, 0.0f);
                    Ci[idx]     = fmaxf(Ai[za]     + ps * vi0, 0.0f);
                    Ci[idx + 1] = fmaxf(Ai[za + 1] + ps * vi1, 0.0f);
                }
            }
        }
}

// ---------------------------------------------------------------------------
// Tensor-core flash attention (bf16x3) — exact R9 version (measured 183 µs).
// 64 q-rows / 4 warps per CTA, 2 CTAs per SM, ldmatrix(+trans) operands.
// ---------------------------------------------------------------------------
#define FSTR 72
#define QPL (64 * FSTR)
#define KPL (64 * FSTR)
#define FLASH_SMEM ((4 * QPL + 4 * KPL) * 2)   // 73728 bytes

__global__ __launch_bounds__(128, 2) void flash_mma_kernel(
    const float* __restrict__ Wr, const float* __restrict__ Wi,
    float* __restrict__ Or, float* __restrict__ Oi)
{
    extern __shared__ uint16_t fsm[];
    uint16_t* QRH = fsm;
    uint16_t* QRL = QRH + QPL;
    uint16_t* QIH = QRL + QPL;
    uint16_t* QIL = QIH + QPL;
    uint16_t* KRH = QIL + QPL;
    uint16_t* KRL = KRH + KPL;
    uint16_t* KIH = KRL + KPL;
    uint16_t* KIL = KIH + KPL;

    int tid = threadIdx.x;
    int lane = tid & 31, w = tid >> 5;   // w in 0..3
    int q0 = blockIdx.x * 64;
    int bh = blockIdx.y;
    int b = bh >> 3, h = bh & 7;

    const float* baseR = Wr + (size_t)b * NSEQ * INNER + h * DH;
    const float* baseI = Wi + (size_t)b * NSEQ * INNER + h * DH;

    #pragma unroll
    for (int i = 0; i < 8; i++) {
        int linear = tid + i * 128;
        int row = linear >> 4, c4 = linear & 15;
        float4 v = *(const float4*)&baseR[(size_t)(q0 + row) * INNER + c4 * 4];
        st_split(QRH, QRL, row * FSTR + c4 * 4, v);
        v = *(const float4*)&baseI[(size_t)(q0 + row) * INNER + c4 * 4];
        st_split(QIH, QIL, row * FSTR + c4 * 4, v);
    }

    int a_off = (16 * w + (lane & 7) + ((lane >> 3) & 1) * 8) * FSTR
              + ((lane >> 4) & 1) * 8;
    int bd_off = ((lane & 7) + ((lane >> 4) & 1) * 8) * FSTR
               + ((lane >> 3) & 1) * 8;
    int bv_off = ((lane & 7) + ((lane >> 3) & 1) * 8) * FSTR
               + ((lane >> 4) & 1) * 8;

    float o_r[8][4] = {}, o_i[8][4] = {};
    float mrow[2] = { -1e30f, -1e30f };
    float lrow[2] = { 0.0f, 0.0f };

    for (int kt = 0; kt < 8; kt++) {
        __syncthreads();
        #pragma unroll
        for (int i = 0; i < 8; i++) {
            int linear = tid + i * 128;
            int key = linear >> 4, c4 = linear & 15;
            int e = key * FSTR + c4 * 4;
            float4 v = *(const float4*)&baseR[(size_t)(kt * 64 + key) * INNER + c4 * 4];
            st_split(KRH, KRL, e, v);
            v = *(const float4*)&baseI[(size_t)(kt * 64 + key) * INNER + c4 * 4];
            st_split(KIH, KIL, e, v);
        }
        __syncthreads();

        // ---- dots ----
        float dr[8][4] = {}, di[8][4] = {};
        #pragma unroll 1
        for (int ks = 0; ks < 4; ks++) {
            int ao = a_off + ks * 16;
            uint32_t aRH[4], aRL[4], aIH[4], aIL[4];
            ldsm4(aRH, QRH + ao); ldsm4(aRL, QRL + ao);
            ldsm4(aIH, QIH + ao); ldsm4(aIL, QIL + ao);
            #pragma unroll
            for (int nfp = 0; nfp < 4; nfp++) {
                int bo = bd_off + nfp * 16 * FSTR + ks * 16;
                uint32_t BRH[4], BRL[4], BIH[4], BIL[4];
                ldsm4(BRH, KRH + bo); ldsm4(BRL, KRL + bo);
                ldsm4(BIH, KIH + bo); ldsm4(BIL, KIL + bo);
                #pragma unroll
                for (int half = 0; half < 2; half++) {
                    int nf = 2 * nfp + half;
                    uint32_t bRH[2] = { BRH[2*half], BRH[2*half+1] };
                    uint32_t bRL[2] = { BRL[2*half], BRL[2*half+1] };
                    uint32_t bIH[2] = { BIH[2*half], BIH[2*half+1] };
                    uint32_t bIL[2] = { BIL[2*half], BIL[2*half+1] };
                    uint32_t nIH[2] = { bIH[0] ^ 0x80008000u, bIH[1] ^ 0x80008000u };
                    uint32_t nIL[2] = { bIL[0] ^ 0x80008000u, bIL[1] ^ 0x80008000u };
                    mma16(dr[nf], aRH, bRH); mma16(dr[nf], aRH, bRL); mma16(dr[nf], aRL, bRH);
                    mma16(dr[nf], aIH, bIH); mma16(dr[nf], aIH, bIL); mma16(dr[nf], aIL, bIH);
                    mma16(di[nf], aIH, bRH); mma16(di[nf], aIH, bRL); mma16(di[nf], aIL, bRH);
                    mma16(di[nf], aRH, nIH); mma16(di[nf], aRH, nIL); mma16(di[nf], aRL, nIH);
                }
            }
        }

        // ---- online softmax ----
        float m2max[2] = { -1.0f, -1.0f };
        #pragma unroll
        for (int nf = 0; nf < 8; nf++)
            #pragma unroll
            for (int e = 0; e < 4; e++) {
                float m2 = dr[nf][e] * dr[nf][e] + di[nf][e] * di[nf][e];
                m2max[e >> 1] = fmaxf(m2max[e >> 1], m2);
            }
        float mnew[2];
        #pragma unroll
        for (int half = 0; half < 2; half++) {
            float v = m2max[half];
            v = fmaxf(v, __shfl_xor_sync(0xffffffffu, v, 1));
            v = fmaxf(v, __shfl_xor_sync(0xffffffffu, v, 2));
            mnew[half] = fmaxf(mrow[half], ASCALE * sqrtf(fmaxf(v, 0.0f)));
        }
        float sc0 = __expf(mrow[0] - mnew[0]);
        float sc1 = __expf(mrow[1] - mnew[1]);
        lrow[0] *= sc0; lrow[1] *= sc1;
        mrow[0] = mnew[0]; mrow[1] = mnew[1];
        #pragma unroll
        for (int nf = 0; nf < 8; nf++) {
            o_r[nf][0] *= sc0; o_r[nf][1] *= sc0;
            o_r[nf][2] *= sc1; o_r[nf][3] *= sc1;
            o_i[nf][0] *= sc0; o_i[nf][1] *= sc0;
            o_i[nf][2] *= sc1; o_i[nf][3] *= sc1;
        }
        float rsum[2] = { 0.0f, 0.0f };
        #pragma unroll
        for (int nf = 0; nf < 8; nf++)
            #pragma unroll
            for (int e = 0; e < 4; e++) {
                float m2 = dr[nf][e] * dr[nf][e] + di[nf][e] * di[nf][e];
                if (m2 > 0.0f) {
                    float rs = rsqrtf(m2);
                    float s = m2 * rs;
                    float p = __expf(ASCALE * s - mrow[e >> 1]);
                    rsum[e >> 1] += p;
                    float f = p * rs;
                    dr[nf][e] *= f;
                    di[nf][e] *= f;
                } else {
                    float p = __expf(-mrow[e >> 1]);
                    rsum[e >> 1] += p;
                    dr[nf][e] = p;
                    di[nf][e] = 0.0f;
                }
            }
        #pragma unroll
        for (int half = 0; half < 2; half++) {
            float v = rsum[half];
            v += __shfl_xor_sync(0xffffffffu, v, 1);
            v += __shfl_xor_sync(0xffffffffu, v, 2);
            lrow[half] += v;
        }

        // ---- AV ----
        #pragma unroll
        for (int t = 0; t < 4; t++) {
            uint32_t PrH[4] = { hi2(dr[2*t][0], dr[2*t][1]),   hi2(dr[2*t][2], dr[2*t][3]),
                                hi2(dr[2*t+1][0], dr[2*t+1][1]), hi2(dr[2*t+1][2], dr[2*t+1][3]) };
            uint32_t PrL[4] = { pkbf(lof(dr[2*t][0]), lof(dr[2*t][1])),
                                pkbf(lof(dr[2*t][2]), lof(dr[2*t][3])),
                                pkbf(lof(dr[2*t+1][0]), lof(dr[2*t+1][1])),
                                pkbf(lof(dr[2*t+1][2]), lof(dr[2*t+1][3])) };
            uint32_t PiH[4] = { hi2(di[2*t][0], di[2*t][1]),   hi2(di[2*t][2], di[2*t][3]),
                                hi2(di[2*t+1][0], di[2*t+1][1]), hi2(di[2*t+1][2], di[2*t+1][3]) };
            uint32_t PiL[4] = { pkbf(lof(di[2*t][0]), lof(di[2*t][1])),
                                pkbf(lof(di[2*t][2]), lof(di[2*t][3])),
                                pkbf(lof(di[2*t+1][0]), lof(di[2*t+1][1])),
                                pkbf(lof(di[2*t+1][2]), lof(di[2*t+1][3])) };
            #pragma unroll
            for (int nfp = 0; nfp < 4; nfp++) {
                int bo = bv_off + t * 16 * FSTR + nfp * 16;
                uint32_t BRH[4], BRL[4], BIH[4], BIL[4];
                ldsm4t(BRH, KRH + bo); ldsm4t(BRL, KRL + bo);
                ldsm4t(BIH, KIH + bo); ldsm4t(BIL, KIL + bo);
                #pragma unroll
                for (int half = 0; half < 2; half++) {
                    int nf = 2 * nfp + half;
                    uint32_t bRH[2] = { BRH[2*half], BRH[2*half+1] };
                    uint32_t bRL[2] = { BRL[2*half], BRL[2*half+1] };
                    uint32_t bIH[2] = { BIH[2*half], BIH[2*half+1] };
                    uint32_t bIL[2] = { BIL[2*half], BIL[2*half+1] };
                    uint32_t nIH[2] = { bIH[0] ^ 0x80008000u, bIH[1] ^ 0x80008000u };
                    uint32_t nIL[2] = { bIL[0] ^ 0x80008000u, bIL[1] ^ 0x80008000u };
                    mma16(o_r[nf], PrH, bRH); mma16(o_r[nf], PrH, bRL); mma16(o_r[nf], PrL, bRH);
                    mma16(o_r[nf], PiH, nIH); mma16(o_r[nf], PiH, nIL); mma16(o_r[nf], PiL, nIH);
                    mma16(o_i[nf], PrH, bIH); mma16(o_i[nf], PrH, bIL); mma16(o_i[nf], PrL, bIH);
                    mma16(o_i[nf], PiH, bRH); mma16(o_i[nf], PiH, bRL); mma16(o_i[nf], PiL, bRH);
                }
            }
        }
    }

    // ---- normalize + write O ----
    int gid = lane >> 2, tig = lane & 3;
    float inv0 = 1.0f / lrow[0];
    float inv1 = 1.0f / lrow[1];
    size_t row0g = (size_t)(b * NSEQ + q0 + 16 * w + gid);
    #pragma unroll
    for (int nf = 0; nf < 8; nf++) {
        int col = h * DH + nf * 8 + tig * 2;
        *(float2*)&Or[row0g * INNER + col] =
            make_float2(o_r[nf][0] * inv0, o_r[nf][1] * inv0);
        *(float2*)&Or[(row0g + 8) * INNER + col] =
            make_float2(o_r[nf][2] * inv1, o_r[nf][3] * inv1);
        *(float2*)&Oi[row0g * INNER + col] =
            make_float2(o_i[nf][0] * inv0, o_i[nf][1] * inv0);
        *(float2*)&Oi[(row0g + 8) * INNER + col] =
            make_float2(o_i[nf][2] * inv1, o_i[nf][3] * inv1);
    }
}

__global__ __launch_bounds__(256) void init_kernel(
    const float* __restrict__ xr, const float* __restrict__ xi)
{
    int i = blockIdx.x * 256 + threadIdx.x;
    g_x_r[i] = xr[i];
    g_x_i[i] = xi[i];
}

__global__ __launch_bounds__(256) void output_kernel(float* __restrict__ out)
{
    int i = blockIdx.x * 256 + threadIdx.x;
    out[i] = g_x_r[i];
    out[i + ROWS * DIMD] = g_x_i[i];
}

// ---------------------------------------------------------------------------
// Launch
// ---------------------------------------------------------------------------
extern "C" void kernel_launch(void* const* d_in, const int* in_sizes, int n_in,
                              void* d_out, int out_size)
{
    const float* x_r   = (const float*)d_in[0];
    const float* x_i   = (const float*)d_in[1];
    const float* ln1gr = (const float*)d_in[2];
    const float* ln1gi = (const float*)d_in[3];
    const float* ln2gr = (const float*)d_in[4];
    const float* ln2gi = (const float*)d_in[5];
    const float* ln1br = (const float*)d_in[6];
    const float* ln1bi = (const float*)d_in[7];
    const float* ln2br = (const float*)d_in[8];
    const float* ln2bi = (const float*)d_in[9];
    const float* qkvwr = (const float*)d_in[10];
    const float* qkvwi = (const float*)d_in[11];
    const float* outwr = (const float*)d_in[12];
    const float* outwi = (const float*)d_in[13];
    const float* outbr = (const float*)d_in[14];
    const float* outbi = (const float*)d_in[15];
    const float* ffwr  = (const float*)d_in[16];
    const float* ffwi  = (const float*)d_in[17];
    const float* stepv = (const float*)d_in[18];
    const float* lambv = (const float*)d_in[19];

    const int EW = ROWS * DIMD;
    const dim3 gemm_grid(DIMD / 128, ROWS / 128);   // (4, 32) = 128 blocks

    float* wr = (float*)d_out;
    float* wi = wr + (size_t)ROWS * INNER;

    float *xr, *xi, *zr, *zi;
    cudaGetSymbolAddress((void**)&xr, g_x_r);
    cudaGetSymbolAddress((void**)&xi, g_x_i);
    cudaGetSymbolAddress((void**)&zr, g_z_r);
    cudaGetSymbolAddress((void**)&zi, g_z_i);

    cudaFuncSetAttribute(flash_mma_kernel,
                         cudaFuncAttributeMaxDynamicSharedMemorySize, FLASH_SMEM);
    cudaFuncSetAttribute(cgemm_bf16x3<0>,
                         cudaFuncAttributeMaxDynamicSharedMemorySize, CG_SMEM);
    cudaFuncSetAttribute(cgemm_bf16x3<1>,
                         cudaFuncAttributeMaxDynamicSharedMemorySize, CG_SMEM);
    cudaFuncSetAttribute(cgemm_bf16x3<2>,
                         cudaFuncAttributeMaxDynamicSharedMemorySize, CG_SMEM);

    init_kernel<<<EW / 256, 256>>>(x_r, x_i);

    for (int l = 0; l < DEPTH; l++) {
        const float* qr  = qkvwr + (size_t)l * INNER * DIMD;
        const float* qi  = qkvwi + (size_t)l * INNER * DIMD;
        const float* owr = outwr + (size_t)l * DIMD * INNER;
        const float* owi = outwi + (size_t)l * DIMD * INNER;
        const float* fwr = ffwr + (size_t)l * DIMD * DIMD;
        const float* fwi = ffwi + (size_t)l * DIMD * DIMD;

        // z1 = CLN(x)
        cln_kernel<<<ROWS, 256>>>(xr, xi,
                                  ln1gr + l * DIMD, ln1br + l * DIMD,
                                  ln1gi + l * DIMD, ln1bi + l * DIMD,
                                  zr, zi);
        // w = z1 @ Wqkv^T   -> d_out scratch
        cgemm_bf16x3<0><<<gemm_grid, 256, CG_SMEM>>>(zr, zi, DIMD, qr, qi, DIMD,
                                                     wr, wi, INNER, DIMD,
                                                     nullptr, nullptr, nullptr, nullptr, 0);
        // ao = attention(w) -> z buffer
        flash_mma_kernel<<<dim3(NSEQ / 64, BB * HEADS), 128, FLASH_SMEM>>>(wr, wi, zr, zi);
        // x += ao @ Wout^T + bias
        cgemm_bf16x3<1><<<gemm_grid, 256, CG_SMEM>>>(zr, zi, INNER, owr, owi, INNER,
                                                     xr, xi, DIMD, INNER,
                                                     outbr + l * DIMD, outbi + l * DIMD,
                                                     nullptr, nullptr, 0);
        // z2 = CLN(x)
        cln_kernel<<<ROWS, 256>>>(xr, xi,
                                  ln2gr + l * DIMD, ln2br + l * DIMD,
                                  ln2gi + l * DIMD, ln2bi + l * DIMD,
                                  zr, zi);
        // x = CReLU(z2 + ps*(z2 @ Wff^T) - ps*pl)
        cgemm_bf16x3<2><<<gemm_grid, 256, CG_SMEM>>>(zr, zi, DIMD, fwr, fwi, DIMD,
                                                     xr, xi, DIMD, DIMD,
                                                     nullptr, nullptr, stepv, lambv, l);
    }

    output_kernel<<<EW / 256, 256>>>((float*)d_out);
}